// round 10
// baseline (speedup 1.0000x reference)
#include <cuda_runtime.h>
#include <math.h>

// GWD loss, single fused kernel, warp-private 4-STAGE cp.async pipeline:
//  - 64-row warp chunks (stage 2816B), 4 stages -> prefetch distance 3
//    => up to 8.4KB in flight per warp (1.5x R8), 96% chunk balance
//  - 45KB smem/block -> 5 blocks/SM, grid 740 = one wave
//  - no __syncthreads in hot loop (only __syncwarp); warps drift freely
//  - 2 rows/lane/iteration from smem (stride-5, conflict-free), approx math
//  - block reduce -> g_partials; last finished block reduces, writes mean

#define NBLOCKS   740    // 148 SMs * 5
#define NTHREADS  128    // 4 warps
#define NWARPS    4
#define WCHUNK    64     // rows per warp-iteration
#define STAGES    4
#define STAGE_F4  176    // pred 80 + targ 80 + wgt 16

__device__ float g_partials[NBLOCKS];
__device__ unsigned int g_count = 0;

__device__ __forceinline__ float f_sqrt(float x) {
    float r; asm("sqrt.approx.f32 %0, %1;" : "=f"(r) : "f"(x)); return r;
}
__device__ __forceinline__ float f_rsqrt(float x) {
    float r; asm("rsqrt.approx.f32 %0, %1;" : "=f"(r) : "f"(x)); return r;
}
__device__ __forceinline__ float f_rcp(float x) {
    float r; asm("rcp.approx.f32 %0, %1;" : "=f"(r) : "f"(x)); return r;
}
__device__ __forceinline__ float f_lg2(float x) {
    float r; asm("lg2.approx.f32 %0, %1;" : "=f"(r) : "f"(x)); return r;
}

__device__ __forceinline__ void cp16(float4* smem, const float4* gmem) {
    unsigned saddr = (unsigned)__cvta_generic_to_shared(smem);
    asm volatile("cp.async.cg.shared.global [%0], [%1], 16;\n"
                 :: "r"(saddr), "l"(gmem));
}

__device__ __forceinline__ float row_loss(
    float xp, float yp, float wp, float hp, float rp,
    float xt, float yt, float wt, float ht, float rt,
    float wgt)
{
    float dx = xp - xt, dy = yp - yt;
    float xyd = dx * dx + dy * dy;

    float cp, sp, ct, st;
    __sincosf(rp, &sp, &cp);
    __sincosf(rt, &st, &ct);

    float w2p = 0.25f * wp * wp, h2p = 0.25f * hp * hp;
    float w2t = 0.25f * wt * wt, h2t = 0.25f * ht * ht;

    float cp2 = cp * cp, sp2 = sp * sp;
    float ct2 = ct * ct, st2 = st * st;

    float a1 = cp2 * w2p + sp2 * h2p;
    float d1 = sp2 * w2p + cp2 * h2p;
    float b1 = cp * sp * (w2p - h2p);

    float a2 = ct2 * w2t + st2 * h2t;
    float d2 = st2 * w2t + ct2 * h2t;
    float b2 = ct * st * (w2t - h2t);

    float trcross = a1 * a2 + 2.0f * b1 * b2 + d1 * d2;
    float prod4   = fabsf(wp * hp * wt * ht);
    float sqdet   = prod4 * 0.0625f;

    float inner = fmaxf(trcross + 2.0f * sqdet, 0.0f);
    float whr   = (w2p + h2p) + (w2t + h2t) - 2.0f * f_sqrt(inner);

    float dist  = f_sqrt(fmaxf(xyd + whr, 0.0f));
    float inv_scale = f_rsqrt(f_sqrt(prod4));   // prod4^(-1/4)
    dist = dist * inv_scale;

    float ln1p = f_lg2(1.0f + dist) * 0.6931471805599453f;
    float loss = 1.0f - f_rcp(1.0f + ln1p);
    return loss * wgt;
}

__global__ __launch_bounds__(NTHREADS, 5)
void gwd_fused_kernel(const float* __restrict__ pred,
                      const float* __restrict__ target,
                      const float* __restrict__ weight,
                      float* __restrict__ out,
                      int n)
{
    // per warp/stage floats: pred [0..319], targ [320..639], wgt [640..703]
    __shared__ float4 s_buf[NWARPS][STAGES][STAGE_F4];   // 45,056 B

    const int tid  = threadIdx.x;
    const int lane = tid & 31;
    const int warp = tid >> 5;

    const int gw = blockIdx.x * NWARPS + warp;   // global warp id
    const int W  = gridDim.x * NWARPS;           // 2960 warps
    const int nchunks = n / WCHUNK;              // 31250 for N=2M (exact)

    float acc = 0.0f;

    auto issue = [&](int c, float4* b) {
        const float4* gp  = (const float4*)(pred   + (long)c * WCHUNK * 5);
        const float4* gt  = (const float4*)(target + (long)c * WCHUNK * 5);
        const float4* gwt = (const float4*)(weight + (long)c * WCHUNK);
        cp16(&b[lane],       &gp[lane]);
        cp16(&b[32 + lane],  &gp[32 + lane]);
        cp16(&b[80 + lane],  &gt[lane]);
        cp16(&b[112 + lane], &gt[32 + lane]);
        if (lane < 16) {
            cp16(&b[64 + lane],  &gp[64 + lane]);
            cp16(&b[144 + lane], &gt[64 + lane]);
            cp16(&b[160 + lane], &gwt[lane]);
        }
    };

    // prologue: issue stages 0..2 (empty commits past end keep counts aligned)
    #pragma unroll
    for (int st = 0; st < STAGES - 1; st++) {
        int cc = gw + st * W;
        if (cc < nchunks) issue(cc, s_buf[warp][st]);
        asm volatile("cp.async.commit_group;\n" ::: "memory");
    }

    int s = 0;
    for (int c = gw; c < nchunks; c += W)
    {
        int cn = c + (STAGES - 1) * W;
        if (cn < nchunks) issue(cn, s_buf[warp][(s + STAGES - 1) & 3]);
        asm volatile("cp.async.commit_group;\n" ::: "memory");
        // allow newest STAGES-1 groups pending -> group for chunk c complete
        asm volatile("cp.async.wait_group %0;\n" :: "n"(STAGES - 1) : "memory");
        __syncwarp();   // cross-lane visibility of stage s

        const float* base = (const float*)s_buf[warp][s];
        #pragma unroll
        for (int k = 0; k < 2; k++) {
            int r = k * 32 + lane;                 // conflict-free stride-5
            const float* p = base + 5 * r;
            const float* t = base + 320 + 5 * r;
            float wgt = base[640 + r];
            acc += row_loss(p[0], p[1], p[2], p[3], p[4],
                            t[0], t[1], t[2], t[3], t[4], wgt);
        }
        __syncwarp();   // done reading stage s before it's re-issued
        s = (s + 1) & 3;
    }

    // tail rows (none for N=2M, kept for generality): block 0 scalar
    int tail_start = nchunks * WCHUNK;
    if (blockIdx.x == 0 && tail_start + tid < n) {
        int i = tail_start + tid;
        const float* p = pred + 5 * (long)i;
        const float* t = target + 5 * (long)i;
        acc += row_loss(p[0], p[1], p[2], p[3], p[4],
                        t[0], t[1], t[2], t[3], t[4], weight[i]);
    }

    // block reduction (barriers only here, outside hot loop)
    __shared__ float s_warp[NWARPS];
    for (int off = 16; off > 0; off >>= 1)
        acc += __shfl_down_sync(0xFFFFFFFFu, acc, off);
    if (lane == 0) s_warp[warp] = acc;
    __syncthreads();

    __shared__ bool s_last;
    if (warp == 0) {
        float v = (lane < NWARPS) ? s_warp[lane] : 0.0f;
        for (int off = 2; off > 0; off >>= 1)
            v += __shfl_down_sync(0xFFFFFFFFu, v, off);
        if (lane == 0) {
            g_partials[blockIdx.x] = v;
            __threadfence();
            unsigned int done = atomicAdd(&g_count, 1u);
            s_last = (done == gridDim.x - 1);
        }
    }
    __syncthreads();

    // last block reduces all partials, vectorized (185 f4 = 740 floats)
    if (s_last) {
        const float4* p4 = (const float4*)g_partials;
        float v = 0.0f;
        int nf4 = NBLOCKS / 4;                     // 185
        for (int k = tid; k < nf4; k += NTHREADS) {
            float4 q = p4[k];
            v += (q.x + q.y) + (q.z + q.w);
        }
        for (int off = 16; off > 0; off >>= 1)
            v += __shfl_down_sync(0xFFFFFFFFu, v, off);
        if (lane == 0) s_warp[warp] = v;
        __syncthreads();
        if (warp == 0) {
            float r = (lane < NWARPS) ? s_warp[lane] : 0.0f;
            for (int off = 2; off > 0; off >>= 1)
                r += __shfl_down_sync(0xFFFFFFFFu, r, off);
            if (lane == 0) {
                out[0] = r / (float)n;
                g_count = 0;   // reset for next graph replay
            }
        }
    }
}

extern "C" void kernel_launch(void* const* d_in, const int* in_sizes, int n_in,
                              void* d_out, int out_size)
{
    const float* pred   = (const float*)d_in[0];
    const float* target = (const float*)d_in[1];
    const float* weight = (const float*)d_in[2];
    float* out = (float*)d_out;

    int n = in_sizes[2];  // weight has N elements

    gwd_fused_kernel<<<NBLOCKS, NTHREADS>>>(pred, target, weight, out, n);
}

// round 11
// speedup vs baseline: 1.2675x; 1.2675x over previous
#include <cuda_runtime.h>
#include <math.h>

// GWD loss, single fused kernel, WARP-PRIVATE double-buffered cp.async (R8 cfg)
// + algebraically reduced row math:
//   tr(Sigma_t Sigma_p) = 2*Sp*St + 2*Dp*Dt*cos(2(rp-rt)),
//     S=(w^2+h^2)/8, D=(w^2-h^2)/8  -> ONE __cosf instead of two __sincosf
//   sqrt(u)/prod^(1/4) = sqrt(u * rsqrt(prod))
//  - 128-row warp chunks, 11 coalesced 16B cp.async/lane, double buffered
//  - no __syncthreads in hot loop; warps drift freely
//  - block reduce -> g_partials; last finished block reduces, writes mean

#define NBLOCKS   740    // 148 SMs * 5 (45KB smem/block)
#define NTHREADS  128    // 4 warps
#define NWARPS    4
#define WCHUNK    128    // rows per warp-iteration
#define STAGE_F4  352    // pred 160 + targ 160 + wgt 32

__device__ float g_partials[NBLOCKS];
__device__ unsigned int g_count = 0;

__device__ __forceinline__ float f_sqrt(float x) {
    float r; asm("sqrt.approx.f32 %0, %1;" : "=f"(r) : "f"(x)); return r;
}
__device__ __forceinline__ float f_rsqrt(float x) {
    float r; asm("rsqrt.approx.f32 %0, %1;" : "=f"(r) : "f"(x)); return r;
}
__device__ __forceinline__ float f_rcp(float x) {
    float r; asm("rcp.approx.f32 %0, %1;" : "=f"(r) : "f"(x)); return r;
}
__device__ __forceinline__ float f_lg2(float x) {
    float r; asm("lg2.approx.f32 %0, %1;" : "=f"(r) : "f"(x)); return r;
}

__device__ __forceinline__ void cp16(float4* smem, const float4* gmem) {
    unsigned saddr = (unsigned)__cvta_generic_to_shared(smem);
    asm volatile("cp.async.cg.shared.global [%0], [%1], 16;\n"
                 :: "r"(saddr), "l"(gmem));
}

__device__ __forceinline__ float row_loss(
    float xp, float yp, float wp, float hp, float rp,
    float xt, float yt, float wt, float ht, float rt,
    float wgt)
{
    float dx = xp - xt, dy = yp - yt;
    float xyd = dx * dx + dy * dy;

    float wp2 = wp * wp, hp2 = hp * hp;
    float wt2 = wt * wt, ht2 = ht * ht;

    float Sp = 0.125f * (wp2 + hp2);    // tr(Sigma_p)/2
    float Dp = 0.125f * (wp2 - hp2);
    float St = 0.125f * (wt2 + ht2);
    float Dt = 0.125f * (wt2 - ht2);

    float cosd = __cosf(2.0f * (rp - rt));
    // tr(Sigma_t Sigma_p):
    float trcross = 2.0f * (Sp * St + Dp * Dt * cosd);

    float prod4 = fabsf(wp * hp * wt * ht);
    // inner = trcross + 2*sqrt(det(cross)) = trcross + prod4/8
    float inner = fmaxf(trcross + 0.125f * prod4, 0.0f);

    // whr = tr_p + tr_t - 2*sqrt(inner) = 2(Sp+St) - 2*sqrt(inner)
    float whr = 2.0f * ((Sp + St) - f_sqrt(inner));

    float u = fmaxf(xyd + whr, 0.0f);
    // dist = sqrt(u)/prod4^(1/4) = sqrt(u * rsqrt(prod4))
    float dist = f_sqrt(u * f_rsqrt(prod4));

    float ln1p = f_lg2(1.0f + dist) * 0.6931471805599453f;
    float loss = 1.0f - f_rcp(1.0f + ln1p);
    return loss * wgt;
}

__global__ __launch_bounds__(NTHREADS, 5)
void gwd_fused_kernel(const float* __restrict__ pred,
                      const float* __restrict__ target,
                      const float* __restrict__ weight,
                      float* __restrict__ out,
                      int n)
{
    // per warp, per stage: [0..159]=pred f4, [160..319]=targ f4, [320..351]=wgt f4
    __shared__ float4 s_buf[NWARPS][2][STAGE_F4];   // 45,056 B

    const int tid  = threadIdx.x;
    const int lane = tid & 31;
    const int warp = tid >> 5;

    const int gw = blockIdx.x * NWARPS + warp;   // global warp id
    const int W  = gridDim.x * NWARPS;           // total warps
    const int nchunks = n / WCHUNK;              // 15625 for N=2M (exact)

    float acc = 0.0f;

    auto issue = [&](int c, float4* b) {
        const float4* gp  = (const float4*)(pred   + (long)c * WCHUNK * 5);
        const float4* gt  = (const float4*)(target + (long)c * WCHUNK * 5);
        const float4* gwt = (const float4*)(weight + (long)c * WCHUNK);
        #pragma unroll
        for (int k = 0; k < 5; k++)
            cp16(&b[k * 32 + lane], &gp[k * 32 + lane]);
        #pragma unroll
        for (int k = 0; k < 5; k++)
            cp16(&b[160 + k * 32 + lane], &gt[k * 32 + lane]);
        cp16(&b[320 + lane], &gwt[lane]);
    };

    int c = gw;
    if (c < nchunks) issue(c, s_buf[warp][0]);
    asm volatile("cp.async.commit_group;\n" ::: "memory");

    int s = 0;
    for (; c < nchunks; c += W)
    {
        int cn = c + W;
        float4* cur = s_buf[warp][s];
        float4* nxt = s_buf[warp][s ^ 1];
        if (cn < nchunks) issue(cn, nxt);
        asm volatile("cp.async.commit_group;\n" ::: "memory");
        asm volatile("cp.async.wait_group 1;\n" ::: "memory");
        __syncwarp();   // cross-lane visibility of cur

        const float* base = (const float*)cur;
        #pragma unroll
        for (int k = 0; k < 4; k++) {
            int r = k * 32 + lane;                 // conflict-free stride-5
            const float* p = base + 5 * r;
            const float* t = base + 640 + 5 * r;
            float wgt = base[1280 + r];
            acc += row_loss(p[0], p[1], p[2], p[3], p[4],
                            t[0], t[1], t[2], t[3], t[4], wgt);
        }
        __syncwarp();   // done reading cur before it's re-issued
        s ^= 1;
    }

    // tail rows (none for N=2M, kept for generality): block 0 scalar
    int tail_start = nchunks * WCHUNK;
    if (blockIdx.x == 0 && tail_start + tid < n) {
        int i = tail_start + tid;
        const float* p = pred + 5 * (long)i;
        const float* t = target + 5 * (long)i;
        acc += row_loss(p[0], p[1], p[2], p[3], p[4],
                        t[0], t[1], t[2], t[3], t[4], weight[i]);
    }

    // block reduction (barriers only here, outside hot loop)
    __shared__ float s_warp[NWARPS];
    for (int off = 16; off > 0; off >>= 1)
        acc += __shfl_down_sync(0xFFFFFFFFu, acc, off);
    if (lane == 0) s_warp[warp] = acc;
    __syncthreads();

    __shared__ bool s_last;
    if (warp == 0) {
        float v = (lane < NWARPS) ? s_warp[lane] : 0.0f;
        for (int off = 2; off > 0; off >>= 1)
            v += __shfl_down_sync(0xFFFFFFFFu, v, off);
        if (lane == 0) {
            g_partials[blockIdx.x] = v;
            __threadfence();
            unsigned int done = atomicAdd(&g_count, 1u);
            s_last = (done == gridDim.x - 1);
        }
    }
    __syncthreads();

    // last block reduces all partials, vectorized (185 f4 = 740 floats)
    if (s_last) {
        const float4* p4 = (const float4*)g_partials;
        float v = 0.0f;
        int nf4 = NBLOCKS / 4;                     // 185
        for (int k = tid; k < nf4; k += NTHREADS) {
            float4 q = p4[k];
            v += (q.x + q.y) + (q.z + q.w);
        }
        for (int off = 16; off > 0; off >>= 1)
            v += __shfl_down_sync(0xFFFFFFFFu, v, off);
        if (lane == 0) s_warp[warp] = v;
        __syncthreads();
        if (warp == 0) {
            float r = (lane < NWARPS) ? s_warp[lane] : 0.0f;
            for (int off = 2; off > 0; off >>= 1)
                r += __shfl_down_sync(0xFFFFFFFFu, r, off);
            if (lane == 0) {
                out[0] = r / (float)n;
                g_count = 0;   // reset for next graph replay
            }
        }
    }
}

extern "C" void kernel_launch(void* const* d_in, const int* in_sizes, int n_in,
                              void* d_out, int out_size)
{
    const float* pred   = (const float*)d_in[0];
    const float* target = (const float*)d_in[1];
    const float* weight = (const float*)d_in[2];
    float* out = (float*)d_out;

    int n = in_sizes[2];  // weight has N elements

    gwd_fused_kernel<<<NBLOCKS, NTHREADS>>>(pred, target, weight, out, n);
}